// round 12
// baseline (speedup 1.0000x reference)
#include <cuda_runtime.h>
#include <cuda_bf16.h>
#include <math.h>
#include <stdint.h>

#define NPIX 4096
#define CCH  512
#define NB   8
#define TOTAL 16777216
#define PI_D 3.14159265358979323846

// ----------------------------- device scratch ------------------------------
__device__ float g_Ak  [512*512];
__device__ float g_Asp [64*64];
__device__ float g_AspT[64*64];
__device__ __nv_bfloat16 g_Akb [512*512];           // [k][c]
__device__ __nv_bfloat16 g_Aspb [64*64];
__device__ __nv_bfloat16 g_AspTb[64*64];
__device__ __nv_bfloat16 g_Mb  [4*128*512];         // fused W1@AkT  [i][o][k]
__device__ __nv_bfloat16 g_W2b [4*9*128*128];
__device__ __nv_bfloat16 g_W3b [4*128*128];
__device__ __nv_bfloat16 g_Dt[(size_t)NB*NPIX*CCH]; // [b][p][k]
__device__ __nv_bfloat16 g_Tb [(size_t)NB*CCH*NPIX];
__device__ __nv_bfloat16 g_Yb [(size_t)4*NB*128*NPIX];
__device__ __nv_bfloat16 g_H1b[(size_t)4*NB*128*NPIX];
__device__ __nv_bfloat16 g_H2b[(size_t)4*NB*128*NPIX];
__device__ unsigned g_hist1[2048];
__device__ unsigned g_hist2[4*16];
__device__ unsigned g_selBin[4];
__device__ unsigned g_selRank[4];
__device__ unsigned g_thr[4];

__device__ __forceinline__ uint32_t smem_u32(const void* p) {
    uint32_t a;
    asm("{ .reg .u64 t; cvta.to.shared.u64 t, %1; cvt.u32.u64 %0, t; }"
        : "=r"(a) : "l"(p));
    return a;
}
__device__ __forceinline__ unsigned pack_bf2(float a, float b) {
    __nv_bfloat162 h;
    h.x = __float2bfloat16(a); h.y = __float2bfloat16(b);
    return *(unsigned*)&h;
}

// ----------------------------- init kernels --------------------------------
__global__ void k_init_dct() {
    int idx = blockIdx.x * blockDim.x + threadIdx.x;
    if (idx < 512*512) {
        int r = idx >> 9, c = idx & 511;
        float a = (float)r * ((float)c + 0.5f) * (float)(PI_D / 512.0);
        float v = cosf(a) * sqrtf(2.f / 512.f);
        if (r == 0) v = cosf(a) * sqrtf(1.f / 512.f);
        g_Ak[r*512 + c] = v;
    }
    if (idx < 64*64) {
        int r = idx >> 6, c = idx & 63;
        float a = (float)r * ((float)c + 0.5f) * (float)(PI_D / 64.0);
        float v = cosf(a) * sqrtf(2.f / 64.f);
        if (r == 0) v = cosf(a) * sqrtf(1.f / 64.f);
        g_Asp [r*64 + c] = v;
        g_AspT[c*64 + r] = v;
    }
}

__global__ void k_prep_b(const float* __restrict__ W2, const float* __restrict__ W3) {
    int idx = blockIdx.x * blockDim.x + threadIdx.x;
    if (idx < 512*512) g_Akb[idx] = __float2bfloat16(g_Ak[idx]);
    if (idx < 64*64) {
        g_Aspb [idx] = __float2bfloat16(g_Asp [idx]);
        g_AspTb[idx] = __float2bfloat16(g_AspT[idx]);
    }
    if (idx < 4*128*128) g_W3b[idx] = __float2bfloat16(W3[idx]);
    if (idx < 4*128*128*9) {
        int i = idx / (128*128*9); int rem = idx % (128*128*9);
        int o = rem / (128*9); rem %= (128*9);
        int c = rem / 9, t = rem % 9;
        g_W2b[((size_t)(i*9 + t)*128 + o)*128 + c] = __float2bfloat16(W2[idx]);
    }
}

// M_i[o][k] = sum_c W1[i][o][c] * Ak[k][c]
__global__ void k_mkM(const float* __restrict__ W1) {
    int idx = blockIdx.x * blockDim.x + threadIdx.x;
    if (idx >= 4*128*512) return;
    int i = idx >> 16;
    int o = (idx >> 9) & 127;
    int k = idx & 511;
    const float4* w = (const float4*)(W1 + ((size_t)i * 128 + o) * 512);
    const float4* a = (const float4*)(g_Ak + (size_t)k * 512);
    float s = 0.f;
#pragma unroll 4
    for (int c4 = 0; c4 < 128; c4++) {
        float4 wv = w[c4], av = a[c4];
        s += wv.x*av.x + wv.y*av.y + wv.z*av.z + wv.w*av.w;
    }
    g_Mb[idx] = __float2bfloat16(s);
}

// ------------- spatial 64x64 two-sided transform on tensor cores ------------
#define SLD 72

__global__ __launch_bounds__(256) void k_sdct(const void* __restrict__ srcv,
                                              int srcBf16,
                                              __nv_bfloat16* __restrict__ dst,
                                              const __nv_bfloat16* __restrict__ Mt,
                                              const float* __restrict__ bias,
                                              int dorelu) {
    __shared__ __nv_bfloat16 sM[64 * SLD];
    __shared__ __nv_bfloat16 sX[4 * 64 * SLD];
    int tid = threadIdx.x, wid = tid >> 5, lane = tid & 31;
    size_t base = (size_t)blockIdx.x * 4 * 4096;

    for (int g = tid; g < 2048; g += 256) {
        int row = g >> 5, c2 = g & 31;
        *(__nv_bfloat162*)&sM[row * SLD + c2 * 2] =
            *(const __nv_bfloat162*)&Mt[row * 64 + c2 * 2];
    }
    if (srcBf16) {
        const __nv_bfloat16* src = (const __nv_bfloat16*)srcv;
        for (int g = tid; g < 8192; g += 256) {
            int s = g >> 11, r = (g >> 5) & 63, c2 = g & 31;
            *(unsigned*)&sX[s * 64 * SLD + r * SLD + c2 * 2] =
                *(const unsigned*)&src[base + (size_t)s * 4096 + r * 64 + c2 * 2];
        }
    } else {
        const float* src = (const float*)srcv;
        for (int g = tid; g < 8192; g += 256) {
            int s = g >> 11, r = (g >> 5) & 63, c2 = g & 31;
            float2 f = *(const float2*)&src[base + (size_t)s * 4096 + r * 64 + c2 * 2];
            *(unsigned*)&sX[s * 64 * SLD + r * SLD + c2 * 2] = pack_bf2(f.x, f.y);
        }
    }
    __syncthreads();

    int s = wid >> 1, band = (wid & 1) * 32;
    __nv_bfloat16* Xs = &sX[s * 64 * SLD];
    int gq = lane >> 2, tq = lane & 3;

    uint32_t aAddr[2], bAddr[8];
#pragma unroll
    for (int mi = 0; mi < 2; mi++)
        aAddr[mi] = smem_u32(&Xs[(band + mi * 16 + (lane & 15)) * SLD + ((lane >> 4) << 3)]);
#pragma unroll
    for (int ni = 0; ni < 8; ni++)
        bAddr[ni] = smem_u32(&sM[(ni * 8 + (lane & 7)) * SLD + (((lane >> 3) & 1) << 3)]);

    float acc[2][8][4];
#pragma unroll
    for (int mi = 0; mi < 2; mi++)
#pragma unroll
        for (int ni = 0; ni < 8; ni++)
#pragma unroll
            for (int q = 0; q < 4; q++) acc[mi][ni][q] = 0.f;

#pragma unroll
    for (int ks = 0; ks < 4; ks++) {
        uint32_t af[2][4], bf[8][2];
#pragma unroll
        for (int mi = 0; mi < 2; mi++)
            asm volatile("ldmatrix.sync.aligned.m8n8.x4.shared.b16 {%0,%1,%2,%3}, [%4];"
                : "=r"(af[mi][0]), "=r"(af[mi][1]), "=r"(af[mi][2]), "=r"(af[mi][3])
                : "r"(aAddr[mi] + ks * 32));
#pragma unroll
        for (int ni = 0; ni < 8; ni++)
            asm volatile("ldmatrix.sync.aligned.m8n8.x2.shared.b16 {%0,%1}, [%2];"
                : "=r"(bf[ni][0]), "=r"(bf[ni][1]) : "r"(bAddr[ni] + ks * 32));
#pragma unroll
        for (int mi = 0; mi < 2; mi++)
#pragma unroll
            for (int ni = 0; ni < 8; ni++)
                asm volatile(
                    "mma.sync.aligned.m16n8k16.row.col.f32.bf16.bf16.f32 "
                    "{%0,%1,%2,%3}, {%4,%5,%6,%7}, {%8,%9}, {%0,%1,%2,%3};"
                    : "+f"(acc[mi][ni][0]), "+f"(acc[mi][ni][1]),
                      "+f"(acc[mi][ni][2]), "+f"(acc[mi][ni][3])
                    : "r"(af[mi][0]), "r"(af[mi][1]), "r"(af[mi][2]), "r"(af[mi][3]),
                      "r"(bf[ni][0]), "r"(bf[ni][1]));
    }
    __syncthreads();

#pragma unroll
    for (int mi = 0; mi < 2; mi++) {
        int m = band + mi * 16 + gq;
#pragma unroll
        for (int ni = 0; ni < 8; ni++) {
            int j0 = ni * 8 + tq * 2;
            Xs[j0 * SLD + m]           = __float2bfloat16(acc[mi][ni][0]);
            Xs[(j0 + 1) * SLD + m]     = __float2bfloat16(acc[mi][ni][1]);
            Xs[j0 * SLD + m + 8]       = __float2bfloat16(acc[mi][ni][2]);
            Xs[(j0 + 1) * SLD + m + 8] = __float2bfloat16(acc[mi][ni][3]);
        }
    }
    __syncthreads();

    uint32_t aAddr2[2], bAddr2[8];
#pragma unroll
    for (int mi = 0; mi < 2; mi++)
        aAddr2[mi] = smem_u32(&sM[(band + mi * 16 + (lane & 15)) * SLD + ((lane >> 4) << 3)]);
#pragma unroll
    for (int ni = 0; ni < 8; ni++)
        bAddr2[ni] = smem_u32(&Xs[(ni * 8 + (lane & 7)) * SLD + (((lane >> 3) & 1) << 3)]);

#pragma unroll
    for (int mi = 0; mi < 2; mi++)
#pragma unroll
        for (int ni = 0; ni < 8; ni++)
#pragma unroll
            for (int q = 0; q < 4; q++) acc[mi][ni][q] = 0.f;

#pragma unroll
    for (int ks = 0; ks < 4; ks++) {
        uint32_t af[2][4], bf[8][2];
#pragma unroll
        for (int mi = 0; mi < 2; mi++)
            asm volatile("ldmatrix.sync.aligned.m8n8.x4.shared.b16 {%0,%1,%2,%3}, [%4];"
                : "=r"(af[mi][0]), "=r"(af[mi][1]), "=r"(af[mi][2]), "=r"(af[mi][3])
                : "r"(aAddr2[mi] + ks * 32));
#pragma unroll
        for (int ni = 0; ni < 8; ni++)
            asm volatile("ldmatrix.sync.aligned.m8n8.x2.shared.b16 {%0,%1}, [%2];"
                : "=r"(bf[ni][0]), "=r"(bf[ni][1]) : "r"(bAddr2[ni] + ks * 32));
#pragma unroll
        for (int mi = 0; mi < 2; mi++)
#pragma unroll
            for (int ni = 0; ni < 8; ni++)
                asm volatile(
                    "mma.sync.aligned.m16n8k16.row.col.f32.bf16.bf16.f32 "
                    "{%0,%1,%2,%3}, {%4,%5,%6,%7}, {%8,%9}, {%0,%1,%2,%3};"
                    : "+f"(acc[mi][ni][0]), "+f"(acc[mi][ni][1]),
                      "+f"(acc[mi][ni][2]), "+f"(acc[mi][ni][3])
                    : "r"(af[mi][0]), "r"(af[mi][1]), "r"(af[mi][2]), "r"(af[mi][3]),
                      "r"(bf[ni][0]), "r"(bf[ni][1]));
    }

    float bval = 0.f;
    if (bias) {
        int sg = blockIdx.x * 4 + s;
        bval = bias[((sg >> 10) << 7) | (sg & 127)];
    }
    __nv_bfloat16* D = dst + base + (size_t)s * 4096;
#pragma unroll
    for (int mi = 0; mi < 2; mi++) {
        int i = band + mi * 16 + gq;
#pragma unroll
        for (int ni = 0; ni < 8; ni++) {
            int j = ni * 8 + tq * 2;
            float a0 = acc[mi][ni][0] + bval, a1 = acc[mi][ni][1] + bval;
            float a2 = acc[mi][ni][2] + bval, a3 = acc[mi][ni][3] + bval;
            if (dorelu) {
                a0 = fmaxf(a0, 0.f); a1 = fmaxf(a1, 0.f);
                a2 = fmaxf(a2, 0.f); a3 = fmaxf(a3, 0.f);
            }
            *(unsigned*)&D[i * 64 + j] = pack_bf2(a0, a1);
            *(unsigned*)&D[(i + 8) * 64 + j] = pack_bf2(a2, a3);
        }
    }
}

// ---- forward channel DCT -> Dt bf16 (transposed) + coarse magnitude hist ----
#define FLD 72
#define FBLD 136

__global__ __launch_bounds__(256) void k_fwdch() {
    __shared__ __align__(16) char buf[36864];
    __shared__ unsigned shist[2048];
    __nv_bfloat16* sA = (__nv_bfloat16*)buf;
    __nv_bfloat16* sB = (__nv_bfloat16*)(buf + 18432);
    __nv_bfloat16* sT = (__nv_bfloat16*)buf;
    int tid = threadIdx.x, wid = tid >> 5, lane = tid & 31;
    int b = blockIdx.z;
    int p0 = blockIdx.x * 128, k0t = blockIdx.y * 128;
    const __nv_bfloat16* A = g_Akb + (size_t)k0t * 512;
    const __nv_bfloat16* B = g_Tb + (size_t)b * 512 * 4096;

    for (int q = tid; q < 2048; q += 256) shist[q] = 0;

    int wm = wid & 1, wn = wid >> 1;
    float acc[4][4][4];
#pragma unroll
    for (int mi = 0; mi < 4; mi++)
#pragma unroll
        for (int ni = 0; ni < 4; ni++)
#pragma unroll
            for (int q = 0; q < 4; q++) acc[mi][ni][q] = 0.f;

    uint32_t aAddr[4], bAddr[4];
#pragma unroll
    for (int mi = 0; mi < 4; mi++) {
        int row = wm * 64 + mi * 16 + (lane & 15);
        int col = (lane >> 4) << 3;
        aAddr[mi] = smem_u32(&sA[row * FLD + col]);
    }
#pragma unroll
    for (int ni = 0; ni < 4; ni++)
        bAddr[ni] = smem_u32(&sB[(lane & 15) * FBLD + wn * 32 + ni * 8]);

    for (int kc = 0; kc < 512; kc += 64) {
        __syncthreads();
#pragma unroll
        for (int ps = 0; ps < 4; ps++) {
            int idx = ps * 256 + tid;
            int row = idx >> 3, slot = idx & 7;
            *(uint4*)&sA[row * FLD + slot * 8] =
                *(const uint4*)&A[(size_t)row * 512 + kc + slot * 8];
        }
#pragma unroll
        for (int g4 = 0; g4 < 4; g4++) {
            int g = g4 * 256 + tid;
            int krow = g >> 4, seg = g & 15;
            *(uint4*)&sB[krow * FBLD + seg * 8] =
                *(const uint4*)&B[(size_t)(kc + krow) * 4096 + p0 + seg * 8];
        }
        __syncthreads();

#pragma unroll
        for (int ks = 0; ks < 4; ks++) {
            uint32_t af[4][4], bf[4][2];
#pragma unroll
            for (int mi = 0; mi < 4; mi++) {
                asm volatile(
                    "ldmatrix.sync.aligned.m8n8.x4.shared.b16 {%0,%1,%2,%3}, [%4];"
                    : "=r"(af[mi][0]), "=r"(af[mi][1]), "=r"(af[mi][2]), "=r"(af[mi][3])
                    : "r"(aAddr[mi] + ks * 32));
            }
#pragma unroll
            for (int ni = 0; ni < 4; ni++) {
                asm volatile(
                    "ldmatrix.sync.aligned.m8n8.x2.trans.shared.b16 {%0,%1}, [%2];"
                    : "=r"(bf[ni][0]), "=r"(bf[ni][1])
                    : "r"(bAddr[ni] + ks * 16 * FBLD * 2));
            }
#pragma unroll
            for (int mi = 0; mi < 4; mi++)
#pragma unroll
                for (int ni = 0; ni < 4; ni++) {
                    asm volatile(
                        "mma.sync.aligned.m16n8k16.row.col.f32.bf16.bf16.f32 "
                        "{%0,%1,%2,%3}, {%4,%5,%6,%7}, {%8,%9}, {%0,%1,%2,%3};"
                        : "+f"(acc[mi][ni][0]), "+f"(acc[mi][ni][1]),
                          "+f"(acc[mi][ni][2]), "+f"(acc[mi][ni][3])
                        : "r"(af[mi][0]), "r"(af[mi][1]), "r"(af[mi][2]), "r"(af[mi][3]),
                          "r"(bf[ni][0]), "r"(bf[ni][1]));
                }
        }
    }
    __syncthreads();

    int gq = lane >> 2, tq = lane & 3;
#pragma unroll
    for (int mi = 0; mi < 4; mi++) {
        int kr = wm * 64 + mi * 16 + gq;
#pragma unroll
        for (int ni = 0; ni < 4; ni++) {
            int pc = wn * 32 + ni * 8 + tq * 2;
            unsigned u01 = pack_bf2(acc[mi][ni][0], acc[mi][ni][1]);
            unsigned u23 = pack_bf2(acc[mi][ni][2], acc[mi][ni][3]);
            sT[pc * FBLD + kr]           = *(__nv_bfloat16*)&u01;
            sT[(pc + 1) * FBLD + kr]     = ((__nv_bfloat16*)&u01)[1];
            sT[pc * FBLD + kr + 8]       = *(__nv_bfloat16*)&u23;
            sT[(pc + 1) * FBLD + kr + 8] = ((__nv_bfloat16*)&u23)[1];
            atomicAdd(&shist[(u01 & 0x7FFFu) >> 4], 1u);
            atomicAdd(&shist[((u01 >> 16) & 0x7FFFu) >> 4], 1u);
            atomicAdd(&shist[(u23 & 0x7FFFu) >> 4], 1u);
            atomicAdd(&shist[((u23 >> 16) & 0x7FFFu) >> 4], 1u);
        }
    }
    __syncthreads();

    {
        int p = tid >> 1, half = tid & 1;
        __nv_bfloat16* dst = g_Dt + (size_t)b * NPIX * CCH
                           + (size_t)(p0 + p) * 512 + k0t + half * 64;
        const uint4* srcv = (const uint4*)&sT[p * FBLD + half * 64];
#pragma unroll
        for (int q = 0; q < 8; q++) ((uint4*)dst)[q] = srcv[q];
    }
    for (int q = tid; q < 2048; q += 256)
        if (shist[q]) atomicAdd(&g_hist1[q], shist[q]);
}

// --------------- bf16-domain threshold selection -----------------
__global__ void k_selc() {
    int i = threadIdx.x;
    if (i >= 4) return;
    unsigned k = (unsigned)(TOTAL >> (2 * (i + 1)));
    unsigned cum = 0;
    for (int bin = 2047; bin >= 0; bin--) {
        unsigned c = g_hist1[bin];
        if (cum + c >= k) { g_selBin[i] = (unsigned)bin; g_selRank[i] = k - cum; return; }
        cum += c;
    }
    g_selBin[i] = 0; g_selRank[i] = 1;
}

__global__ void k_ref() {
    __shared__ unsigned sh[64];
    if (threadIdx.x < 64) sh[threadIdx.x] = 0;
    __syncthreads();
    unsigned s0 = g_selBin[0], s1 = g_selBin[1], s2 = g_selBin[2], s3 = g_selBin[3];
    const uint4* Dt4 = (const uint4*)g_Dt;
    long n4 = TOTAL / 8;
    for (long idx = (long)blockIdx.x * blockDim.x + threadIdx.x; idx < n4;
         idx += (long)gridDim.x * blockDim.x) {
        uint4 v = Dt4[idx];
        unsigned ws[4] = {v.x, v.y, v.z, v.w};
#pragma unroll
        for (int j = 0; j < 4; j++) {
#pragma unroll
            for (int hh = 0; hh < 2; hh++) {
                unsigned mag = (ws[j] >> (hh * 16)) & 0x7FFFu;
                unsigned cb = mag >> 4, lb = mag & 15u;
                if (cb == s0) atomicAdd(&sh[lb], 1u);
                if (cb == s1) atomicAdd(&sh[16 + lb], 1u);
                if (cb == s2) atomicAdd(&sh[32 + lb], 1u);
                if (cb == s3) atomicAdd(&sh[48 + lb], 1u);
            }
        }
    }
    __syncthreads();
    if (threadIdx.x < 64 && sh[threadIdx.x])
        atomicAdd(&g_hist2[threadIdx.x], sh[threadIdx.x]);
}

__global__ void k_self() {
    int i = threadIdx.x;
    if (i >= 4) return;
    unsigned r = g_selRank[i];
    unsigned cum = 0;
    for (int s = 15; s >= 0; s--) {
        unsigned c = g_hist2[i * 16 + s];
        if (cum + c >= r) { g_thr[i] = (g_selBin[i] << 4) | (unsigned)s; return; }
        cum += c;
    }
    g_thr[i] = g_selBin[i] << 4;
}

// ------------- unified tensor-core GEMM/conv (bf16 in/out) ------------------
#define LDA 72
#define LDBB 136

__global__ __launch_bounds__(256, 2) void k_cmma(
    const __nv_bfloat16* __restrict__ Abase, long aI, long tapStride, int Ktap, int ntap,
    const __nv_bfloat16* __restrict__ Bbase, long bI, long bB,
    __nv_bfloat16* __restrict__ Cbase, long cI, long cB,
    const float* __restrict__ bias, int relu, int NI)
{
    __shared__ __nv_bfloat16 sA[128 * LDA];
    __shared__ __nv_bfloat16 sB[64 * LDBB];
    int tid = threadIdx.x, wid = tid >> 5, lane = tid & 31;
    int z = blockIdx.z;
    int b = z / NI, i = z % NI;
    int p0 = blockIdx.x * 128;
    int m0 = blockIdx.y * 128;
    const __nv_bfloat16* A = Abase + (size_t)i * aI;
    const __nv_bfloat16* B = Bbase + (size_t)i * bI + (size_t)b * bB;
    __nv_bfloat16* C = Cbase + (size_t)i * cI + (size_t)b * cB;

    int wm = wid & 1, wn = wid >> 1;
    float acc[4][4][4];
#pragma unroll
    for (int mi = 0; mi < 4; mi++)
#pragma unroll
        for (int ni = 0; ni < 4; ni++)
#pragma unroll
            for (int q = 0; q < 4; q++) acc[mi][ni][q] = 0.f;

    uint32_t aAddr[4], bAddr[4];
#pragma unroll
    for (int mi = 0; mi < 4; mi++) {
        int row = wm * 64 + mi * 16 + (lane & 15);
        int col = (lane >> 4) << 3;
        aAddr[mi] = smem_u32(&sA[row * LDA + col]);
    }
#pragma unroll
    for (int ni = 0; ni < 4; ni++)
        bAddr[ni] = smem_u32(&sB[(lane & 15) * LDBB + wn * 32 + ni * 8]);

    for (int t = 0; t < ntap; t++) {
        int dy2 = (ntap == 9) ? (t / 3 - 1) * 2 : 0;
        int dx2 = (ntap == 9) ? (t % 3 - 1) * 2 : 0;
        const __nv_bfloat16* At = A + (size_t)t * tapStride;
        for (int kc = 0; kc < Ktap; kc += 64) {
            __syncthreads();
#pragma unroll
            for (int ps = 0; ps < 4; ps++) {
                int idx = ps * 256 + tid;
                int row = idx >> 3, slot = idx & 7;
                *(uint4*)&sA[row * LDA + slot * 8] =
                    *(const uint4*)&At[(size_t)(m0 + row) * Ktap + kc + slot * 8];
            }
#pragma unroll
            for (int g4 = 0; g4 < 4; g4++) {
                int g = g4 * 256 + tid;
                int krow = g >> 4, seg = g & 15;
                int p = p0 + seg * 8;
                int m = p >> 6, n = p & 63;
                int mm = m + dy2;
                bool rowok = (unsigned)mm < 64u;
                const __nv_bfloat16* src = B + (size_t)(kc + krow) * 4096 + mm * 64;
                unsigned pk[4];
                int nlo = n + dx2;
                if (rowok && nlo >= 0 && (n + 7 + dx2) < 64) {
#pragma unroll
                    for (int jj = 0; jj < 4; jj++)
                        pk[jj] = *(const unsigned*)&src[nlo + jj * 2];
                } else {
                    const unsigned short z16 = 0;
#pragma unroll
                    for (int jj = 0; jj < 4; jj++) {
                        int n0e = n + jj * 2 + dx2, n1e = n0e + 1;
                        unsigned short e0 = (rowok && (unsigned)n0e < 64u)
                            ? *(const unsigned short*)&src[n0e] : z16;
                        unsigned short e1 = (rowok && (unsigned)n1e < 64u)
                            ? *(const unsigned short*)&src[n1e] : z16;
                        pk[jj] = (unsigned)e0 | ((unsigned)e1 << 16);
                    }
                }
                *(uint4*)&sB[krow * LDBB + seg * 8] = make_uint4(pk[0], pk[1], pk[2], pk[3]);
            }
            __syncthreads();

#pragma unroll
            for (int ks = 0; ks < 4; ks++) {
                uint32_t af[4][4], bf[4][2];
#pragma unroll
                for (int mi = 0; mi < 4; mi++) {
                    asm volatile(
                        "ldmatrix.sync.aligned.m8n8.x4.shared.b16 {%0,%1,%2,%3}, [%4];"
                        : "=r"(af[mi][0]), "=r"(af[mi][1]), "=r"(af[mi][2]), "=r"(af[mi][3])
                        : "r"(aAddr[mi] + ks * 32));
                }
#pragma unroll
                for (int ni = 0; ni < 4; ni++) {
                    asm volatile(
                        "ldmatrix.sync.aligned.m8n8.x2.trans.shared.b16 {%0,%1}, [%2];"
                        : "=r"(bf[ni][0]), "=r"(bf[ni][1])
                        : "r"(bAddr[ni] + ks * 16 * LDBB * 2));
                }
#pragma unroll
                for (int mi = 0; mi < 4; mi++)
#pragma unroll
                    for (int ni = 0; ni < 4; ni++) {
                        asm volatile(
                            "mma.sync.aligned.m16n8k16.row.col.f32.bf16.bf16.f32 "
                            "{%0,%1,%2,%3}, {%4,%5,%6,%7}, {%8,%9}, {%0,%1,%2,%3};"
                            : "+f"(acc[mi][ni][0]), "+f"(acc[mi][ni][1]),
                              "+f"(acc[mi][ni][2]), "+f"(acc[mi][ni][3])
                            : "r"(af[mi][0]), "r"(af[mi][1]), "r"(af[mi][2]), "r"(af[mi][3]),
                              "r"(bf[ni][0]), "r"(bf[ni][1]));
                    }
            }
        }
    }

    int gq = lane >> 2, tq = lane & 3;
#pragma unroll
    for (int mi = 0; mi < 4; mi++) {
        int ol = wm * 64 + mi * 16 + gq;
        float bv0 = bias ? bias[i * 128 + ol] : 0.f;
        float bv1 = bias ? bias[i * 128 + ol + 8] : 0.f;
#pragma unroll
        for (int ni = 0; ni < 4; ni++) {
            int col = p0 + wn * 32 + ni * 8 + tq * 2;
            float a0 = acc[mi][ni][0] + bv0, a1 = acc[mi][ni][1] + bv0;
            float a2 = acc[mi][ni][2] + bv1, a3 = acc[mi][ni][3] + bv1;
            if (relu) {
                a0 = fmaxf(a0, 0.f); a1 = fmaxf(a1, 0.f);
                a2 = fmaxf(a2, 0.f); a3 = fmaxf(a3, 0.f);
            }
            *(unsigned*)&C[(size_t)(m0 + ol) * 4096 + col] = pack_bf2(a0, a1);
            *(unsigned*)&C[(size_t)(m0 + ol + 8) * 4096 + col] = pack_bf2(a2, a3);
        }
    }
}

// ---- fused masked (channel-inverse + conv1): Y[i][b][o][p] = M_i @ mask_i(D[b]) ----
#define LDB 72

__device__ __forceinline__ unsigned mask2(unsigned w, unsigned thrb) {
    unsigned lo = w & 0x7FFFu, hi = (w >> 16) & 0x7FFFu;
    unsigned r = w;
    if (lo < thrb) r &= 0xFFFF0000u;
    if (hi < thrb) r &= 0x0000FFFFu;
    return r;
}

__global__ __launch_bounds__(256, 2) void k_fmma() {
    __shared__ __nv_bfloat16 sA[128 * LDB];
    __shared__ __nv_bfloat16 sB[128 * LDB];
    int tid = threadIdx.x, wid = tid >> 5, lane = tid & 31;
    int z = blockIdx.z;
    int b = z >> 2, i = z & 3;
    int n0 = blockIdx.x * 128;
    unsigned thrb = g_thr[i];

    const uint4* Ag = (const uint4*)(g_Mb + (size_t)i * 128 * 512);
    const uint4* Bg = (const uint4*)(g_Dt + (size_t)b * NPIX * CCH);

    int wm = wid & 1;
    int wn = wid >> 1;

    float acc[4][4][4];
#pragma unroll
    for (int mi = 0; mi < 4; mi++)
#pragma unroll
        for (int ni = 0; ni < 4; ni++)
#pragma unroll
            for (int q = 0; q < 4; q++) acc[mi][ni][q] = 0.f;

    uint32_t aAddr[4], bAddr[4];
#pragma unroll
    for (int mi = 0; mi < 4; mi++) {
        int row = wm * 64 + mi * 16 + (lane & 15);
        int col = (lane >> 4) << 3;
        aAddr[mi] = smem_u32(&sA[row * LDB + col]);
    }
#pragma unroll
    for (int ni = 0; ni < 4; ni++) {
        int row = wn * 32 + ni * 8 + (lane & 7);
        int col = ((lane >> 3) & 1) << 3;
        bAddr[ni] = smem_u32(&sB[row * LDB + col]);
    }

    for (int ch = 0; ch < 8; ch++) {
        int k0 = ch * 64;
        uint4 av[4], bv[4];
#pragma unroll
        for (int ps = 0; ps < 4; ps++) {
            int idx = ps * 256 + tid;
            int row = idx >> 3, slot = idx & 7;
            av[ps] = Ag[(((size_t)row * 512 + k0) >> 3) + slot];
            bv[ps] = Bg[(((size_t)(n0 + row) * 512 + k0) >> 3) + slot];
            bv[ps].x = mask2(bv[ps].x, thrb);
            bv[ps].y = mask2(bv[ps].y, thrb);
            bv[ps].z = mask2(bv[ps].z, thrb);
            bv[ps].w = mask2(bv[ps].w, thrb);
        }
        __syncthreads();
#pragma unroll
        for (int ps = 0; ps < 4; ps++) {
            int idx = ps * 256 + tid;
            int row = idx >> 3, slot = idx & 7;
            *(uint4*)&sA[row * LDB + slot * 8] = av[ps];
            *(uint4*)&sB[row * LDB + slot * 8] = bv[ps];
        }
        __syncthreads();

#pragma unroll
        for (int ks = 0; ks < 4; ks++) {
            uint32_t af[4][4], bf[4][2];
#pragma unroll
            for (int mi = 0; mi < 4; mi++) {
                asm volatile(
                    "ldmatrix.sync.aligned.m8n8.x4.shared.b16 {%0,%1,%2,%3}, [%4];"
                    : "=r"(af[mi][0]), "=r"(af[mi][1]), "=r"(af[mi][2]), "=r"(af[mi][3])
                    : "r"(aAddr[mi] + ks * 32));
            }
#pragma unroll
            for (int ni = 0; ni < 4; ni++) {
                asm volatile(
                    "ldmatrix.sync.aligned.m8n8.x2.shared.b16 {%0,%1}, [%2];"
                    : "=r"(bf[ni][0]), "=r"(bf[ni][1])
                    : "r"(bAddr[ni] + ks * 32));
            }
#pragma unroll
            for (int mi = 0; mi < 4; mi++)
#pragma unroll
                for (int ni = 0; ni < 4; ni++) {
                    asm volatile(
                        "mma.sync.aligned.m16n8k16.row.col.f32.bf16.bf16.f32 "
                        "{%0,%1,%2,%3}, {%4,%5,%6,%7}, {%8,%9}, {%0,%1,%2,%3};"
                        : "+f"(acc[mi][ni][0]), "+f"(acc[mi][ni][1]),
                          "+f"(acc[mi][ni][2]), "+f"(acc[mi][ni][3])
                        : "r"(af[mi][0]), "r"(af[mi][1]), "r"(af[mi][2]), "r"(af[mi][3]),
                          "r"(bf[ni][0]), "r"(bf[ni][1]));
                }
        }
    }

    __nv_bfloat16* C = g_Yb + (size_t)((i * 8 + b) * 128) * 4096;
    int gq = lane >> 2, tq = lane & 3;
#pragma unroll
    for (int mi = 0; mi < 4; mi++) {
        int row = wm * 64 + mi * 16 + gq;
#pragma unroll
        for (int ni = 0; ni < 4; ni++) {
            int col = n0 + wn * 32 + ni * 8 + tq * 2;
            *(unsigned*)&C[(size_t)row * 4096 + col] =
                pack_bf2(acc[mi][ni][0], acc[mi][ni][1]);
            *(unsigned*)&C[(size_t)(row + 8) * 4096 + col] =
                pack_bf2(acc[mi][ni][2], acc[mi][ni][3]);
        }
    }
}

// -------- fused conv3 + softmax + residual gate (per 64-pixel tile) ---------
// sL[512][CSLD] bf16 logits tile, then online softmax + x*(1+w)
#define CSLD 72
#define CS_SL   (512 * CSLD * 2)                 // 73728 B
#define CS_SA   (128 * 72 * 2)                   // 18432 B
#define CS_SB   (64 * 72 * 2)                    // 9216 B
#define CS_SMEM (CS_SL + CS_SA + CS_SB)

__global__ __launch_bounds__(256) void k_cs(const float* __restrict__ x,
                                            float* __restrict__ out,
                                            const float* __restrict__ b3) {
    extern __shared__ __align__(16) char dynb[];
    __nv_bfloat16* sL = (__nv_bfloat16*)dynb;
    __nv_bfloat16* sA = (__nv_bfloat16*)(dynb + CS_SL);
    __nv_bfloat16* sB = (__nv_bfloat16*)(dynb + CS_SL + CS_SA);
    __shared__ float s_m[64], s_s[64];
    int tid = threadIdx.x, wid = tid >> 5, lane = tid & 31;
    int p0 = blockIdx.x * 64, b = blockIdx.y;

    int wm = wid & 1, wn = wid >> 1;
    uint32_t aAddr[4], bAddr[2];
#pragma unroll
    for (int mi = 0; mi < 4; mi++) {
        int row = wm * 64 + mi * 16 + (lane & 15);
        int col = (lane >> 4) << 3;
        aAddr[mi] = smem_u32(&sA[row * 72 + col]);
    }
#pragma unroll
    for (int ni = 0; ni < 2; ni++)
        bAddr[ni] = smem_u32(&sB[(lane & 15) * 72 + wn * 16 + ni * 8]);
    int gq = lane >> 2, tq = lane & 3;

    for (int i = 0; i < 4; i++) {
        const __nv_bfloat16* A = g_W3b + (size_t)i * 128 * 128;
        const __nv_bfloat16* B = g_H2b + (size_t)(i * 8 + b) * 128 * 4096;
        float acc[4][2][4];
#pragma unroll
        for (int mi = 0; mi < 4; mi++)
#pragma unroll
            for (int ni = 0; ni < 2; ni++)
#pragma unroll
                for (int q = 0; q < 4; q++) acc[mi][ni][q] = 0.f;

        for (int kc = 0; kc < 128; kc += 64) {
            __syncthreads();
#pragma unroll
            for (int ps = 0; ps < 4; ps++) {
                int idx = ps * 256 + tid;
                int row = idx >> 3, slot = idx & 7;
                *(uint4*)&sA[row * 72 + slot * 8] =
                    *(const uint4*)&A[(size_t)row * 128 + kc + slot * 8];
            }
#pragma unroll
            for (int g2 = 0; g2 < 2; g2++) {
                int g = g2 * 256 + tid;
                int krow = g >> 3, seg = g & 7;
                *(uint4*)&sB[krow * 72 + seg * 8] =
                    *(const uint4*)&B[(size_t)(kc + krow) * 4096 + p0 + seg * 8];
            }
            __syncthreads();

#pragma unroll
            for (int ks = 0; ks < 4; ks++) {
                uint32_t af[4][4], bf[2][2];
#pragma unroll
                for (int mi = 0; mi < 4; mi++) {
                    asm volatile(
                        "ldmatrix.sync.aligned.m8n8.x4.shared.b16 {%0,%1,%2,%3}, [%4];"
                        : "=r"(af[mi][0]), "=r"(af[mi][1]), "=r"(af[mi][2]), "=r"(af[mi][3])
                        : "r"(aAddr[mi] + ks * 32));
                }
#pragma unroll
                for (int ni = 0; ni < 2; ni++) {
                    asm volatile(
                        "ldmatrix.sync.aligned.m8n8.x2.trans.shared.b16 {%0,%1}, [%2];"
                        : "=r"(bf[ni][0]), "=r"(bf[ni][1])
                        : "r"(bAddr[ni] + ks * 16 * 72 * 2));
                }
#pragma unroll
                for (int mi = 0; mi < 4; mi++)
#pragma unroll
                    for (int ni = 0; ni < 2; ni++) {
                        asm volatile(
                            "mma.sync.aligned.m16n8k16.row.col.f32.bf16.bf16.f32 "
                            "{%0,%1,%2,%3}, {%4,%5,%6,%7}, {%8,%9}, {%0,%1,%2,%3};"
                            : "+f"(acc[mi][ni][0]), "+f"(acc[mi][ni][1]),
                              "+f"(acc[mi][ni][2]), "+f"(acc[mi][ni][3])
                            : "r"(af[mi][0]), "r"(af[mi][1]), "r"(af[mi][2]), "r"(af[mi][3]),
                              "r"(bf[ni][0]), "r"(bf[ni][1]));
                    }
            }
        }
        // epilogue -> sL rows i*128.. (bias + relu, bf16)
#pragma unroll
        for (int mi = 0; mi < 4; mi++) {
            int ol = wm * 64 + mi * 16 + gq;
            float bv0 = b3[i * 128 + ol];
            float bv1 = b3[i * 128 + ol + 8];
#pragma unroll
            for (int ni = 0; ni < 2; ni++) {
                int col = wn * 16 + ni * 8 + tq * 2;
                float a0 = fmaxf(acc[mi][ni][0] + bv0, 0.f);
                float a1 = fmaxf(acc[mi][ni][1] + bv0, 0.f);
                float a2 = fmaxf(acc[mi][ni][2] + bv1, 0.f);
                float a3 = fmaxf(acc[mi][ni][3] + bv1, 0.f);
                *(unsigned*)&sL[(i * 128 + ol) * CSLD + col] = pack_bf2(a0, a1);
                *(unsigned*)&sL[(i * 128 + ol + 8) * CSLD + col] = pack_bf2(a2, a3);
            }
        }
    }
    __syncthreads();

    // softmax stats per pixel (threads 0..63)
    if (tid < 64) {
        float m = 0.f, s = 0.f;
#pragma unroll 8
        for (int c = 0; c < 512; c++) {
            float v = __bfloat162float(sL[c * CSLD + tid]);
            float mn = fmaxf(m, v);
            s = s * __expf(m - mn) + __expf(v - mn);
            m = mn;
        }
        s_m[tid] = m;
        s_s[tid] = 1.f / s;
    }
    __syncthreads();

    // gate: thread t -> pixel p = t&63, channel group (t>>6)*128
    {
        int p = tid & 63, cg = (tid >> 6) * 128;
        float m = s_m[p], inv = s_s[p];
        const float* xp = x + (size_t)b * 512 * 4096 + p0 + p;
        float* op = out + (size_t)b * 512 * 4096 + p0 + p;
#pragma unroll 8
        for (int c = cg; c < cg + 128; c++) {
            float w = __expf(__bfloat162float(sL[c * CSLD + p]) - m) * inv;
            float xv = xp[(size_t)c * 4096];
            op[(size_t)c * 4096] = fmaf(xv, w, xv);
        }
    }
}

// ------------------------------- launcher -----------------------------------
extern "C" void kernel_launch(void* const* d_in, const int* in_sizes, int n_in,
                              void* d_out, int out_size) {
    (void)in_sizes; (void)n_in; (void)out_size;
    const float* x  = (const float*)d_in[0];
    const float* W1 = (const float*)d_in[1];
    const float* b1 = (const float*)d_in[2];
    const float* W2 = (const float*)d_in[3];
    const float* b2 = (const float*)d_in[4];
    const float* W3 = (const float*)d_in[5];
    const float* b3 = (const float*)d_in[6];
    float* out = (float*)d_out;

    __nv_bfloat16 *pW2b, *pAspb, *pAspTb, *pTb, *pYb, *pH1b, *pH2b;
    unsigned *ph1, *ph2;
    cudaGetSymbolAddress((void**)&pAspb, g_Aspb);
    cudaGetSymbolAddress((void**)&pAspTb, g_AspTb);
    cudaGetSymbolAddress((void**)&pW2b, g_W2b);
    cudaGetSymbolAddress((void**)&pTb,  g_Tb);
    cudaGetSymbolAddress((void**)&pYb,  g_Yb);
    cudaGetSymbolAddress((void**)&pH1b, g_H1b);
    cudaGetSymbolAddress((void**)&pH2b, g_H2b);
    cudaGetSymbolAddress((void**)&ph1, g_hist1);
    cudaGetSymbolAddress((void**)&ph2, g_hist2);

    cudaFuncSetAttribute(k_cs, cudaFuncAttributeMaxDynamicSharedMemorySize, CS_SMEM);

    k_init_dct<<<1024, 256>>>();
    k_prep_b<<<2304, 256>>>(W2, W3);
    k_mkM<<<1024, 256>>>(W1);
    cudaMemsetAsync(ph1, 0, 2048 * sizeof(unsigned));
    cudaMemsetAsync(ph2, 0, 64 * sizeof(unsigned));

    // forward spatial DCT: x (fp32) -> Tb (bf16)
    k_sdct<<<1024, 256>>>(x, 0, pTb, pAspb, nullptr, 0);

    // forward channel DCT -> Dt bf16 (transposed) + coarse histogram
    k_fwdch<<<dim3(32, 4, 8), 256>>>();

    // bf16-domain exact rank-k thresholds
    k_selc<<<1, 4>>>();
    k_ref<<<2048, 256>>>();
    k_self<<<1, 4>>>();

    // fused masked channel-inverse + conv1 -> Yb (bf16)
    k_fmma<<<dim3(32, 1, 32), 256>>>();

    // inverse spatial DCT + bias + relu: Yb -> H1b
    k_sdct<<<1024, 256>>>(pYb, 1, pH1b, pAspTb, b1, 1);

    // conv2: 3x3 dil-2 + bias + relu
    k_cmma<<<dim3(32, 1, 32), 256>>>(pW2b, 9L*128*128, 128L*128, 128, 9,
                                     pH1b, 8L*128*4096, 128L*4096,
                                     pH2b, 8L*128*4096, 128L*4096,
                                     b2, 1, 4);

    // fused conv3 + softmax + residual gate
    k_cs<<<dim3(64, 8), 256, CS_SMEM>>>(x, out, b3);
}

// round 13
// speedup vs baseline: 1.7014x; 1.7014x over previous
#include <cuda_runtime.h>
#include <cuda_bf16.h>
#include <math.h>
#include <stdint.h>

#define NPIX 4096
#define CCH  512
#define NB   8
#define TOTAL 16777216
#define PI_D 3.14159265358979323846

// ----------------------------- device scratch ------------------------------
__device__ float g_Ak  [512*512];
__device__ float g_Asp [64*64];
__device__ float g_AspT[64*64];
__device__ __nv_bfloat16 g_Akb [512*512];           // [k][c]
__device__ __nv_bfloat16 g_Aspb [64*64];
__device__ __nv_bfloat16 g_AspTb[64*64];
__device__ __nv_bfloat16 g_Mb  [4*128*512];         // fused W1@AkT  [i][o][k]
__device__ __nv_bfloat16 g_W2b [4*9*128*128];
__device__ __nv_bfloat16 g_W3b [4*128*128];
__device__ __nv_bfloat16 g_Dt[(size_t)NB*NPIX*CCH]; // [b][p][k]
__device__ __nv_bfloat16 g_Tb [(size_t)NB*CCH*NPIX];
__device__ __nv_bfloat16 g_Yb [(size_t)4*NB*128*NPIX];
__device__ __nv_bfloat16 g_H1b[(size_t)4*NB*128*NPIX];
__device__ __nv_bfloat16 g_H2b[(size_t)4*NB*128*NPIX];
__device__ __nv_bfloat16 g_Lb [(size_t)NB*CCH*NPIX];
__device__ unsigned g_hist1[2048];
__device__ unsigned g_hist2[4*16];
__device__ unsigned g_selBin[4];
__device__ unsigned g_selRank[4];
__device__ unsigned g_thr[4];

__device__ __forceinline__ uint32_t smem_u32(const void* p) {
    uint32_t a;
    asm("{ .reg .u64 t; cvta.to.shared.u64 t, %1; cvt.u32.u64 %0, t; }"
        : "=r"(a) : "l"(p));
    return a;
}
__device__ __forceinline__ unsigned pack_bf2(float a, float b) {
    __nv_bfloat162 h;
    h.x = __float2bfloat16(a); h.y = __float2bfloat16(b);
    return *(unsigned*)&h;
}

// ----------------------------- init kernels --------------------------------
__global__ void k_init_dct() {
    int idx = blockIdx.x * blockDim.x + threadIdx.x;
    if (idx < 512*512) {
        int r = idx >> 9, c = idx & 511;
        float a = (float)r * ((float)c + 0.5f) * (float)(PI_D / 512.0);
        float v = cosf(a) * sqrtf(2.f / 512.f);
        if (r == 0) v = cosf(a) * sqrtf(1.f / 512.f);
        g_Ak[r*512 + c] = v;
    }
    if (idx < 64*64) {
        int r = idx >> 6, c = idx & 63;
        float a = (float)r * ((float)c + 0.5f) * (float)(PI_D / 64.0);
        float v = cosf(a) * sqrtf(2.f / 64.f);
        if (r == 0) v = cosf(a) * sqrtf(1.f / 64.f);
        g_Asp [r*64 + c] = v;
        g_AspT[c*64 + r] = v;
    }
}

__global__ void k_prep_b(const float* __restrict__ W2, const float* __restrict__ W3) {
    int idx = blockIdx.x * blockDim.x + threadIdx.x;
    if (idx < 512*512) g_Akb[idx] = __float2bfloat16(g_Ak[idx]);
    if (idx < 64*64) {
        g_Aspb [idx] = __float2bfloat16(g_Asp [idx]);
        g_AspTb[idx] = __float2bfloat16(g_AspT[idx]);
    }
    if (idx < 4*128*128) g_W3b[idx] = __float2bfloat16(W3[idx]);
    if (idx < 4*128*128*9) {
        int i = idx / (128*128*9); int rem = idx % (128*128*9);
        int o = rem / (128*9); rem %= (128*9);
        int c = rem / 9, t = rem % 9;
        g_W2b[((size_t)(i*9 + t)*128 + o)*128 + c] = __float2bfloat16(W2[idx]);
    }
}

// M[m][k] = sum_c W1[m][c] * Ak[k][c]   (m = i*128+o)  — tiled 64x64 GEMM
__global__ __launch_bounds__(256) void k_mkM(const float* __restrict__ W1) {
    __shared__ float sW [32][68];
    __shared__ float sAk[32][68];
    int m0 = blockIdx.y * 64, n0 = blockIdx.x * 64;
    int tid = threadIdx.x;
    int r0 = (tid >> 4) * 4, c0n = (tid & 15) * 4;
    float acc[4][4];
#pragma unroll
    for (int ii = 0; ii < 4; ii++)
#pragma unroll
        for (int jj = 0; jj < 4; jj++) acc[ii][jj] = 0.f;

    for (int c0 = 0; c0 < 512; c0 += 32) {
#pragma unroll
        for (int ps = 0; ps < 2; ps++) {
            int idx = ps * 256 + tid;
            int row = idx >> 3, slot = idx & 7;
            float4 w = *(const float4*)&W1[(size_t)(m0 + row) * 512 + c0 + slot * 4];
            float4 a = *(const float4*)&g_Ak[(size_t)(n0 + row) * 512 + c0 + slot * 4];
            sW [slot*4+0][row] = w.x; sW [slot*4+1][row] = w.y;
            sW [slot*4+2][row] = w.z; sW [slot*4+3][row] = w.w;
            sAk[slot*4+0][row] = a.x; sAk[slot*4+1][row] = a.y;
            sAk[slot*4+2][row] = a.z; sAk[slot*4+3][row] = a.w;
        }
        __syncthreads();
#pragma unroll
        for (int cc = 0; cc < 32; cc++) {
            float4 av = *(const float4*)&sW[cc][r0];
            float4 bv = *(const float4*)&sAk[cc][c0n];
            float aa[4] = {av.x, av.y, av.z, av.w};
            float bb[4] = {bv.x, bv.y, bv.z, bv.w};
#pragma unroll
            for (int ii = 0; ii < 4; ii++)
#pragma unroll
                for (int jj = 0; jj < 4; jj++)
                    acc[ii][jj] = fmaf(aa[ii], bb[jj], acc[ii][jj]);
        }
        __syncthreads();
    }
#pragma unroll
    for (int ii = 0; ii < 4; ii++)
#pragma unroll
        for (int jj = 0; jj < 4; jj += 2)
            *(unsigned*)&g_Mb[(size_t)(m0 + r0 + ii) * 512 + n0 + c0n + jj] =
                pack_bf2(acc[ii][jj], acc[ii][jj + 1]);
}

// ------------- spatial 64x64 two-sided transform on tensor cores ------------
#define SLD 72

__global__ __launch_bounds__(256) void k_sdct(const void* __restrict__ srcv,
                                              int srcBf16,
                                              __nv_bfloat16* __restrict__ dst,
                                              const __nv_bfloat16* __restrict__ Mt,
                                              const float* __restrict__ bias,
                                              int dorelu) {
    __shared__ __nv_bfloat16 sM[64 * SLD];
    __shared__ __nv_bfloat16 sX[4 * 64 * SLD];
    int tid = threadIdx.x, wid = tid >> 5, lane = tid & 31;
    size_t base = (size_t)blockIdx.x * 4 * 4096;

    for (int g = tid; g < 2048; g += 256) {
        int row = g >> 5, c2 = g & 31;
        *(__nv_bfloat162*)&sM[row * SLD + c2 * 2] =
            *(const __nv_bfloat162*)&Mt[row * 64 + c2 * 2];
    }
    if (srcBf16) {
        const __nv_bfloat16* src = (const __nv_bfloat16*)srcv;
        for (int g = tid; g < 8192; g += 256) {
            int s = g >> 11, r = (g >> 5) & 63, c2 = g & 31;
            *(unsigned*)&sX[s * 64 * SLD + r * SLD + c2 * 2] =
                *(const unsigned*)&src[base + (size_t)s * 4096 + r * 64 + c2 * 2];
        }
    } else {
        const float* src = (const float*)srcv;
        for (int g = tid; g < 8192; g += 256) {
            int s = g >> 11, r = (g >> 5) & 63, c2 = g & 31;
            float2 f = *(const float2*)&src[base + (size_t)s * 4096 + r * 64 + c2 * 2];
            *(unsigned*)&sX[s * 64 * SLD + r * SLD + c2 * 2] = pack_bf2(f.x, f.y);
        }
    }
    __syncthreads();

    int s = wid >> 1, band = (wid & 1) * 32;
    __nv_bfloat16* Xs = &sX[s * 64 * SLD];
    int gq = lane >> 2, tq = lane & 3;

    uint32_t aAddr[2], bAddr[8];
#pragma unroll
    for (int mi = 0; mi < 2; mi++)
        aAddr[mi] = smem_u32(&Xs[(band + mi * 16 + (lane & 15)) * SLD + ((lane >> 4) << 3)]);
#pragma unroll
    for (int ni = 0; ni < 8; ni++)
        bAddr[ni] = smem_u32(&sM[(ni * 8 + (lane & 7)) * SLD + (((lane >> 3) & 1) << 3)]);

    float acc[2][8][4];
#pragma unroll
    for (int mi = 0; mi < 2; mi++)
#pragma unroll
        for (int ni = 0; ni < 8; ni++)
#pragma unroll
            for (int q = 0; q < 4; q++) acc[mi][ni][q] = 0.f;

#pragma unroll
    for (int ks = 0; ks < 4; ks++) {
        uint32_t af[2][4], bf[8][2];
#pragma unroll
        for (int mi = 0; mi < 2; mi++)
            asm volatile("ldmatrix.sync.aligned.m8n8.x4.shared.b16 {%0,%1,%2,%3}, [%4];"
                : "=r"(af[mi][0]), "=r"(af[mi][1]), "=r"(af[mi][2]), "=r"(af[mi][3])
                : "r"(aAddr[mi] + ks * 32));
#pragma unroll
        for (int ni = 0; ni < 8; ni++)
            asm volatile("ldmatrix.sync.aligned.m8n8.x2.shared.b16 {%0,%1}, [%2];"
                : "=r"(bf[ni][0]), "=r"(bf[ni][1]) : "r"(bAddr[ni] + ks * 32));
#pragma unroll
        for (int mi = 0; mi < 2; mi++)
#pragma unroll
            for (int ni = 0; ni < 8; ni++)
                asm volatile(
                    "mma.sync.aligned.m16n8k16.row.col.f32.bf16.bf16.f32 "
                    "{%0,%1,%2,%3}, {%4,%5,%6,%7}, {%8,%9}, {%0,%1,%2,%3};"
                    : "+f"(acc[mi][ni][0]), "+f"(acc[mi][ni][1]),
                      "+f"(acc[mi][ni][2]), "+f"(acc[mi][ni][3])
                    : "r"(af[mi][0]), "r"(af[mi][1]), "r"(af[mi][2]), "r"(af[mi][3]),
                      "r"(bf[ni][0]), "r"(bf[ni][1]));
    }
    __syncthreads();

#pragma unroll
    for (int mi = 0; mi < 2; mi++) {
        int m = band + mi * 16 + gq;
#pragma unroll
        for (int ni = 0; ni < 8; ni++) {
            int j0 = ni * 8 + tq * 2;
            Xs[j0 * SLD + m]           = __float2bfloat16(acc[mi][ni][0]);
            Xs[(j0 + 1) * SLD + m]     = __float2bfloat16(acc[mi][ni][1]);
            Xs[j0 * SLD + m + 8]       = __float2bfloat16(acc[mi][ni][2]);
            Xs[(j0 + 1) * SLD + m + 8] = __float2bfloat16(acc[mi][ni][3]);
        }
    }
    __syncthreads();

    uint32_t aAddr2[2], bAddr2[8];
#pragma unroll
    for (int mi = 0; mi < 2; mi++)
        aAddr2[mi] = smem_u32(&sM[(band + mi * 16 + (lane & 15)) * SLD + ((lane >> 4) << 3)]);
#pragma unroll
    for (int ni = 0; ni < 8; ni++)
        bAddr2[ni] = smem_u32(&Xs[(ni * 8 + (lane & 7)) * SLD + (((lane >> 3) & 1) << 3)]);

#pragma unroll
    for (int mi = 0; mi < 2; mi++)
#pragma unroll
        for (int ni = 0; ni < 8; ni++)
#pragma unroll
            for (int q = 0; q < 4; q++) acc[mi][ni][q] = 0.f;

#pragma unroll
    for (int ks = 0; ks < 4; ks++) {
        uint32_t af[2][4], bf[8][2];
#pragma unroll
        for (int mi = 0; mi < 2; mi++)
            asm volatile("ldmatrix.sync.aligned.m8n8.x4.shared.b16 {%0,%1,%2,%3}, [%4];"
                : "=r"(af[mi][0]), "=r"(af[mi][1]), "=r"(af[mi][2]), "=r"(af[mi][3])
                : "r"(aAddr2[mi] + ks * 32));
#pragma unroll
        for (int ni = 0; ni < 8; ni++)
            asm volatile("ldmatrix.sync.aligned.m8n8.x2.shared.b16 {%0,%1}, [%2];"
                : "=r"(bf[ni][0]), "=r"(bf[ni][1]) : "r"(bAddr2[ni] + ks * 32));
#pragma unroll
        for (int mi = 0; mi < 2; mi++)
#pragma unroll
            for (int ni = 0; ni < 8; ni++)
                asm volatile(
                    "mma.sync.aligned.m16n8k16.row.col.f32.bf16.bf16.f32 "
                    "{%0,%1,%2,%3}, {%4,%5,%6,%7}, {%8,%9}, {%0,%1,%2,%3};"
                    : "+f"(acc[mi][ni][0]), "+f"(acc[mi][ni][1]),
                      "+f"(acc[mi][ni][2]), "+f"(acc[mi][ni][3])
                    : "r"(af[mi][0]), "r"(af[mi][1]), "r"(af[mi][2]), "r"(af[mi][3]),
                      "r"(bf[ni][0]), "r"(bf[ni][1]));
    }

    float bval = 0.f;
    if (bias) {
        int sg = blockIdx.x * 4 + s;
        bval = bias[((sg >> 10) << 7) | (sg & 127)];
    }
    __nv_bfloat16* D = dst + base + (size_t)s * 4096;
#pragma unroll
    for (int mi = 0; mi < 2; mi++) {
        int i = band + mi * 16 + gq;
#pragma unroll
        for (int ni = 0; ni < 8; ni++) {
            int j = ni * 8 + tq * 2;
            float a0 = acc[mi][ni][0] + bval, a1 = acc[mi][ni][1] + bval;
            float a2 = acc[mi][ni][2] + bval, a3 = acc[mi][ni][3] + bval;
            if (dorelu) {
                a0 = fmaxf(a0, 0.f); a1 = fmaxf(a1, 0.f);
                a2 = fmaxf(a2, 0.f); a3 = fmaxf(a3, 0.f);
            }
            *(unsigned*)&D[i * 64 + j] = pack_bf2(a0, a1);
            *(unsigned*)&D[(i + 8) * 64 + j] = pack_bf2(a2, a3);
        }
    }
}

// ---- forward channel DCT -> Dt bf16 (transposed) + coarse magnitude hist ----
#define FLD 72
#define FBLD 136

__global__ __launch_bounds__(256) void k_fwdch() {
    __shared__ __align__(16) char buf[36864];
    __shared__ unsigned shist[2048];
    __nv_bfloat16* sA = (__nv_bfloat16*)buf;
    __nv_bfloat16* sB = (__nv_bfloat16*)(buf + 18432);
    __nv_bfloat16* sT = (__nv_bfloat16*)buf;
    int tid = threadIdx.x, wid = tid >> 5, lane = tid & 31;
    int b = blockIdx.z;
    int p0 = blockIdx.x * 128, k0t = blockIdx.y * 128;
    const __nv_bfloat16* A = g_Akb + (size_t)k0t * 512;
    const __nv_bfloat16* B = g_Tb + (size_t)b * 512 * 4096;

    for (int q = tid; q < 2048; q += 256) shist[q] = 0;

    int wm = wid & 1, wn = wid >> 1;
    float acc[4][4][4];
#pragma unroll
    for (int mi = 0; mi < 4; mi++)
#pragma unroll
        for (int ni = 0; ni < 4; ni++)
#pragma unroll
            for (int q = 0; q < 4; q++) acc[mi][ni][q] = 0.f;

    uint32_t aAddr[4], bAddr[4];
#pragma unroll
    for (int mi = 0; mi < 4; mi++) {
        int row = wm * 64 + mi * 16 + (lane & 15);
        int col = (lane >> 4) << 3;
        aAddr[mi] = smem_u32(&sA[row * FLD + col]);
    }
#pragma unroll
    for (int ni = 0; ni < 4; ni++)
        bAddr[ni] = smem_u32(&sB[(lane & 15) * FBLD + wn * 32 + ni * 8]);

    for (int kc = 0; kc < 512; kc += 64) {
        __syncthreads();
#pragma unroll
        for (int ps = 0; ps < 4; ps++) {
            int idx = ps * 256 + tid;
            int row = idx >> 3, slot = idx & 7;
            *(uint4*)&sA[row * FLD + slot * 8] =
                *(const uint4*)&A[(size_t)row * 512 + kc + slot * 8];
        }
#pragma unroll
        for (int g4 = 0; g4 < 4; g4++) {
            int g = g4 * 256 + tid;
            int krow = g >> 4, seg = g & 15;
            *(uint4*)&sB[krow * FBLD + seg * 8] =
                *(const uint4*)&B[(size_t)(kc + krow) * 4096 + p0 + seg * 8];
        }
        __syncthreads();

#pragma unroll
        for (int ks = 0; ks < 4; ks++) {
            uint32_t af[4][4], bf[4][2];
#pragma unroll
            for (int mi = 0; mi < 4; mi++) {
                asm volatile(
                    "ldmatrix.sync.aligned.m8n8.x4.shared.b16 {%0,%1,%2,%3}, [%4];"
                    : "=r"(af[mi][0]), "=r"(af[mi][1]), "=r"(af[mi][2]), "=r"(af[mi][3])
                    : "r"(aAddr[mi] + ks * 32));
            }
#pragma unroll
            for (int ni = 0; ni < 4; ni++) {
                asm volatile(
                    "ldmatrix.sync.aligned.m8n8.x2.trans.shared.b16 {%0,%1}, [%2];"
                    : "=r"(bf[ni][0]), "=r"(bf[ni][1])
                    : "r"(bAddr[ni] + ks * 16 * FBLD * 2));
            }
#pragma unroll
            for (int mi = 0; mi < 4; mi++)
#pragma unroll
                for (int ni = 0; ni < 4; ni++) {
                    asm volatile(
                        "mma.sync.aligned.m16n8k16.row.col.f32.bf16.bf16.f32 "
                        "{%0,%1,%2,%3}, {%4,%5,%6,%7}, {%8,%9}, {%0,%1,%2,%3};"
                        : "+f"(acc[mi][ni][0]), "+f"(acc[mi][ni][1]),
                          "+f"(acc[mi][ni][2]), "+f"(acc[mi][ni][3])
                        : "r"(af[mi][0]), "r"(af[mi][1]), "r"(af[mi][2]), "r"(af[mi][3]),
                          "r"(bf[ni][0]), "r"(bf[ni][1]));
                }
        }
    }
    __syncthreads();

    int gq = lane >> 2, tq = lane & 3;
#pragma unroll
    for (int mi = 0; mi < 4; mi++) {
        int kr = wm * 64 + mi * 16 + gq;
#pragma unroll
        for (int ni = 0; ni < 4; ni++) {
            int pc = wn * 32 + ni * 8 + tq * 2;
            unsigned u01 = pack_bf2(acc[mi][ni][0], acc[mi][ni][1]);
            unsigned u23 = pack_bf2(acc[mi][ni][2], acc[mi][ni][3]);
            sT[pc * FBLD + kr]           = *(__nv_bfloat16*)&u01;
            sT[(pc + 1) * FBLD + kr]     = ((__nv_bfloat16*)&u01)[1];
            sT[pc * FBLD + kr + 8]       = *(__nv_bfloat16*)&u23;
            sT[(pc + 1) * FBLD + kr + 8] = ((__nv_bfloat16*)&u23)[1];
            atomicAdd(&shist[(u01 & 0x7FFFu) >> 4], 1u);
            atomicAdd(&shist[((u01 >> 16) & 0x7FFFu) >> 4], 1u);
            atomicAdd(&shist[(u23 & 0x7FFFu) >> 4], 1u);
            atomicAdd(&shist[((u23 >> 16) & 0x7FFFu) >> 4], 1u);
        }
    }
    __syncthreads();

    {
        int p = tid >> 1, half = tid & 1;
        __nv_bfloat16* dst = g_Dt + (size_t)b * NPIX * CCH
                           + (size_t)(p0 + p) * 512 + k0t + half * 64;
        const uint4* srcv = (const uint4*)&sT[p * FBLD + half * 64];
#pragma unroll
        for (int q = 0; q < 8; q++) ((uint4*)dst)[q] = srcv[q];
    }
    for (int q = tid; q < 2048; q += 256)
        if (shist[q]) atomicAdd(&g_hist1[q], shist[q]);
}

// --------------- bf16-domain threshold selection -----------------
__global__ void k_selc() {
    int i = threadIdx.x;
    if (i >= 4) return;
    unsigned k = (unsigned)(TOTAL >> (2 * (i + 1)));
    unsigned cum = 0;
    for (int bin = 2047; bin >= 0; bin--) {
        unsigned c = g_hist1[bin];
        if (cum + c >= k) { g_selBin[i] = (unsigned)bin; g_selRank[i] = k - cum; return; }
        cum += c;
    }
    g_selBin[i] = 0; g_selRank[i] = 1;
}

__global__ void k_ref() {
    __shared__ unsigned sh[64];
    if (threadIdx.x < 64) sh[threadIdx.x] = 0;
    __syncthreads();
    unsigned s0 = g_selBin[0], s1 = g_selBin[1], s2 = g_selBin[2], s3 = g_selBin[3];
    const uint4* Dt4 = (const uint4*)g_Dt;
    long n4 = TOTAL / 8;
    for (long idx = (long)blockIdx.x * blockDim.x + threadIdx.x; idx < n4;
         idx += (long)gridDim.x * blockDim.x) {
        uint4 v = Dt4[idx];
        unsigned ws[4] = {v.x, v.y, v.z, v.w};
#pragma unroll
        for (int j = 0; j < 4; j++) {
#pragma unroll
            for (int hh = 0; hh < 2; hh++) {
                unsigned mag = (ws[j] >> (hh * 16)) & 0x7FFFu;
                unsigned cb = mag >> 4, lb = mag & 15u;
                if (cb == s0) atomicAdd(&sh[lb], 1u);
                if (cb == s1) atomicAdd(&sh[16 + lb], 1u);
                if (cb == s2) atomicAdd(&sh[32 + lb], 1u);
                if (cb == s3) atomicAdd(&sh[48 + lb], 1u);
            }
        }
    }
    __syncthreads();
    if (threadIdx.x < 64 && sh[threadIdx.x])
        atomicAdd(&g_hist2[threadIdx.x], sh[threadIdx.x]);
}

__global__ void k_self() {
    int i = threadIdx.x;
    if (i >= 4) return;
    unsigned r = g_selRank[i];
    unsigned cum = 0;
    for (int s = 15; s >= 0; s--) {
        unsigned c = g_hist2[i * 16 + s];
        if (cum + c >= r) { g_thr[i] = (g_selBin[i] << 4) | (unsigned)s; return; }
        cum += c;
    }
    g_thr[i] = g_selBin[i] << 4;
}

// ------------- unified tensor-core GEMM/conv (bf16 in/out) ------------------
#define LDA 72
#define LDBB 136

__global__ __launch_bounds__(256, 2) void k_cmma(
    const __nv_bfloat16* __restrict__ Abase, long aI, long tapStride, int Ktap, int ntap,
    const __nv_bfloat16* __restrict__ Bbase, long bI, long bB,
    __nv_bfloat16* __restrict__ Cbase, long cI, long cB,
    const float* __restrict__ bias, int relu, int NI)
{
    __shared__ __nv_bfloat16 sA[128 * LDA];
    __shared__ __nv_bfloat16 sB[64 * LDBB];
    int tid = threadIdx.x, wid = tid >> 5, lane = tid & 31;
    int z = blockIdx.z;
    int b = z / NI, i = z % NI;
    int p0 = blockIdx.x * 128;
    int m0 = blockIdx.y * 128;
    const __nv_bfloat16* A = Abase + (size_t)i * aI;
    const __nv_bfloat16* B = Bbase + (size_t)i * bI + (size_t)b * bB;
    __nv_bfloat16* C = Cbase + (size_t)i * cI + (size_t)b * cB;

    int wm = wid & 1, wn = wid >> 1;
    float acc[4][4][4];
#pragma unroll
    for (int mi = 0; mi < 4; mi++)
#pragma unroll
        for (int ni = 0; ni < 4; ni++)
#pragma unroll
            for (int q = 0; q < 4; q++) acc[mi][ni][q] = 0.f;

    uint32_t aAddr[4], bAddr[4];
#pragma unroll
    for (int mi = 0; mi < 4; mi++) {
        int row = wm * 64 + mi * 16 + (lane & 15);
        int col = (lane >> 4) << 3;
        aAddr[mi] = smem_u32(&sA[row * LDA + col]);
    }
#pragma unroll
    for (int ni = 0; ni < 4; ni++)
        bAddr[ni] = smem_u32(&sB[(lane & 15) * LDBB + wn * 32 + ni * 8]);

    for (int t = 0; t < ntap; t++) {
        int dy2 = (ntap == 9) ? (t / 3 - 1) * 2 : 0;
        int dx2 = (ntap == 9) ? (t % 3 - 1) * 2 : 0;
        const __nv_bfloat16* At = A + (size_t)t * tapStride;
        for (int kc = 0; kc < Ktap; kc += 64) {
            __syncthreads();
#pragma unroll
            for (int ps = 0; ps < 4; ps++) {
                int idx = ps * 256 + tid;
                int row = idx >> 3, slot = idx & 7;
                *(uint4*)&sA[row * LDA + slot * 8] =
                    *(const uint4*)&At[(size_t)(m0 + row) * Ktap + kc + slot * 8];
            }
#pragma unroll
            for (int g4 = 0; g4 < 4; g4++) {
                int g = g4 * 256 + tid;
                int krow = g >> 4, seg = g & 15;
                int p = p0 + seg * 8;
                int m = p >> 6, n = p & 63;
                int mm = m + dy2;
                bool rowok = (unsigned)mm < 64u;
                const __nv_bfloat16* src = B + (size_t)(kc + krow) * 4096 + mm * 64;
                unsigned pk[4];
                int nlo = n + dx2;
                if (rowok && nlo >= 0 && (n + 7 + dx2) < 64) {
#pragma unroll
                    for (int jj = 0; jj < 4; jj++)
                        pk[jj] = *(const unsigned*)&src[nlo + jj * 2];
                } else {
                    const unsigned short z16 = 0;
#pragma unroll
                    for (int jj = 0; jj < 4; jj++) {
                        int n0e = n + jj * 2 + dx2, n1e = n0e + 1;
                        unsigned short e0 = (rowok && (unsigned)n0e < 64u)
                            ? *(const unsigned short*)&src[n0e] : z16;
                        unsigned short e1 = (rowok && (unsigned)n1e < 64u)
                            ? *(const unsigned short*)&src[n1e] : z16;
                        pk[jj] = (unsigned)e0 | ((unsigned)e1 << 16);
                    }
                }
                *(uint4*)&sB[krow * LDBB + seg * 8] = make_uint4(pk[0], pk[1], pk[2], pk[3]);
            }
            __syncthreads();

#pragma unroll
            for (int ks = 0; ks < 4; ks++) {
                uint32_t af[4][4], bf[4][2];
#pragma unroll
                for (int mi = 0; mi < 4; mi++) {
                    asm volatile(
                        "ldmatrix.sync.aligned.m8n8.x4.shared.b16 {%0,%1,%2,%3}, [%4];"
                        : "=r"(af[mi][0]), "=r"(af[mi][1]), "=r"(af[mi][2]), "=r"(af[mi][3])
                        : "r"(aAddr[mi] + ks * 32));
                }
#pragma unroll
                for (int ni = 0; ni < 4; ni++) {
                    asm volatile(
                        "ldmatrix.sync.aligned.m8n8.x2.trans.shared.b16 {%0,%1}, [%2];"
                        : "=r"(bf[ni][0]), "=r"(bf[ni][1])
                        : "r"(bAddr[ni] + ks * 16 * LDBB * 2));
                }
#pragma unroll
                for (int mi = 0; mi < 4; mi++)
#pragma unroll
                    for (int ni = 0; ni < 4; ni++) {
                        asm volatile(
                            "mma.sync.aligned.m16n8k16.row.col.f32.bf16.bf16.f32 "
                            "{%0,%1,%2,%3}, {%4,%5,%6,%7}, {%8,%9}, {%0,%1,%2,%3};"
                            : "+f"(acc[mi][ni][0]), "+f"(acc[mi][ni][1]),
                              "+f"(acc[mi][ni][2]), "+f"(acc[mi][ni][3])
                            : "r"(af[mi][0]), "r"(af[mi][1]), "r"(af[mi][2]), "r"(af[mi][3]),
                              "r"(bf[ni][0]), "r"(bf[ni][1]));
                    }
            }
        }
    }

    int gq = lane >> 2, tq = lane & 3;
#pragma unroll
    for (int mi = 0; mi < 4; mi++) {
        int ol = wm * 64 + mi * 16 + gq;
        float bv0 = bias ? bias[i * 128 + ol] : 0.f;
        float bv1 = bias ? bias[i * 128 + ol + 8] : 0.f;
#pragma unroll
        for (int ni = 0; ni < 4; ni++) {
            int col = p0 + wn * 32 + ni * 8 + tq * 2;
            float a0 = acc[mi][ni][0] + bv0, a1 = acc[mi][ni][1] + bv0;
            float a2 = acc[mi][ni][2] + bv1, a3 = acc[mi][ni][3] + bv1;
            if (relu) {
                a0 = fmaxf(a0, 0.f); a1 = fmaxf(a1, 0.f);
                a2 = fmaxf(a2, 0.f); a3 = fmaxf(a3, 0.f);
            }
            *(unsigned*)&C[(size_t)(m0 + ol) * 4096 + col] = pack_bf2(a0, a1);
            *(unsigned*)&C[(size_t)(m0 + ol + 8) * 4096 + col] = pack_bf2(a2, a3);
        }
    }
}

// ---- fused masked (channel-inverse + conv1): Y[i][b][o][p] = M_i @ mask_i(D[b]) ----
#define LDB 72

__device__ __forceinline__ unsigned mask2(unsigned w, unsigned thrb) {
    unsigned lo = w & 0x7FFFu, hi = (w >> 16) & 0x7FFFu;
    unsigned r = w;
    if (lo < thrb) r &= 0xFFFF0000u;
    if (hi < thrb) r &= 0x0000FFFFu;
    return r;
}

__global__ __launch_bounds__(256, 2) void k_fmma() {
    __shared__ __nv_bfloat16 sA[128 * LDB];
    __shared__ __nv_bfloat16 sB[128 * LDB];
    int tid = threadIdx.x, wid = tid >> 5, lane = tid & 31;
    int z = blockIdx.z;
    int b = z >> 2, i = z & 3;
    int n0 = blockIdx.x * 128;
    unsigned thrb = g_thr[i];

    const uint4* Ag = (const uint4*)(g_Mb + (size_t)i * 128 * 512);
    const uint4* Bg = (const uint4*)(g_Dt + (size_t)b * NPIX * CCH);

    int wm = wid & 1;
    int wn = wid >> 1;

    float acc[4][4][4];
#pragma unroll
    for (int mi = 0; mi < 4; mi++)
#pragma unroll
        for (int ni = 0; ni < 4; ni++)
#pragma unroll
            for (int q = 0; q < 4; q++) acc[mi][ni][q] = 0.f;

    uint32_t aAddr[4], bAddr[4];
#pragma unroll
    for (int mi = 0; mi < 4; mi++) {
        int row = wm * 64 + mi * 16 + (lane & 15);
        int col = (lane >> 4) << 3;
        aAddr[mi] = smem_u32(&sA[row * LDB + col]);
    }
#pragma unroll
    for (int ni = 0; ni < 4; ni++) {
        int row = wn * 32 + ni * 8 + (lane & 7);
        int col = ((lane >> 3) & 1) << 3;
        bAddr[ni] = smem_u32(&sB[row * LDB + col]);
    }

    for (int ch = 0; ch < 8; ch++) {
        int k0 = ch * 64;
        uint4 av[4], bv[4];
#pragma unroll
        for (int ps = 0; ps < 4; ps++) {
            int idx = ps * 256 + tid;
            int row = idx >> 3, slot = idx & 7;
            av[ps] = Ag[(((size_t)row * 512 + k0) >> 3) + slot];
            bv[ps] = Bg[(((size_t)(n0 + row) * 512 + k0) >> 3) + slot];
            bv[ps].x = mask2(bv[ps].x, thrb);
            bv[ps].y = mask2(bv[ps].y, thrb);
            bv[ps].z = mask2(bv[ps].z, thrb);
            bv[ps].w = mask2(bv[ps].w, thrb);
        }
        __syncthreads();
#pragma unroll
        for (int ps = 0; ps < 4; ps++) {
            int idx = ps * 256 + tid;
            int row = idx >> 3, slot = idx & 7;
            *(uint4*)&sA[row * LDB + slot * 8] = av[ps];
            *(uint4*)&sB[row * LDB + slot * 8] = bv[ps];
        }
        __syncthreads();

#pragma unroll
        for (int ks = 0; ks < 4; ks++) {
            uint32_t af[4][4], bf[4][2];
#pragma unroll
            for (int mi = 0; mi < 4; mi++) {
                asm volatile(
                    "ldmatrix.sync.aligned.m8n8.x4.shared.b16 {%0,%1,%2,%3}, [%4];"
                    : "=r"(af[mi][0]), "=r"(af[mi][1]), "=r"(af[mi][2]), "=r"(af[mi][3])
                    : "r"(aAddr[mi] + ks * 32));
            }
#pragma unroll
            for (int ni = 0; ni < 4; ni++) {
                asm volatile(
                    "ldmatrix.sync.aligned.m8n8.x2.shared.b16 {%0,%1}, [%2];"
                    : "=r"(bf[ni][0]), "=r"(bf[ni][1])
                    : "r"(bAddr[ni] + ks * 32));
            }
#pragma unroll
            for (int mi = 0; mi < 4; mi++)
#pragma unroll
                for (int ni = 0; ni < 4; ni++) {
                    asm volatile(
                        "mma.sync.aligned.m16n8k16.row.col.f32.bf16.bf16.f32 "
                        "{%0,%1,%2,%3}, {%4,%5,%6,%7}, {%8,%9}, {%0,%1,%2,%3};"
                        : "+f"(acc[mi][ni][0]), "+f"(acc[mi][ni][1]),
                          "+f"(acc[mi][ni][2]), "+f"(acc[mi][ni][3])
                        : "r"(af[mi][0]), "r"(af[mi][1]), "r"(af[mi][2]), "r"(af[mi][3]),
                          "r"(bf[ni][0]), "r"(bf[ni][1]));
                }
        }
    }

    __nv_bfloat16* C = g_Yb + (size_t)((i * 8 + b) * 128) * 4096;
    int gq = lane >> 2, tq = lane & 3;
#pragma unroll
    for (int mi = 0; mi < 4; mi++) {
        int row = wm * 64 + mi * 16 + gq;
#pragma unroll
        for (int ni = 0; ni < 4; ni++) {
            int col = n0 + wn * 32 + ni * 8 + tq * 2;
            *(unsigned*)&C[(size_t)row * 4096 + col] =
                pack_bf2(acc[mi][ni][0], acc[mi][ni][1]);
            *(unsigned*)&C[(size_t)(row + 8) * 4096 + col] =
                pack_bf2(acc[mi][ni][2], acc[mi][ni][3]);
        }
    }
}

// ------------------- softmax (online) + residual gate -----------------------
__global__ __launch_bounds__(128) void k_softmax(const float* __restrict__ x,
                                                 float* __restrict__ out) {
    int b = blockIdx.y;
    int p = blockIdx.x * 128 + threadIdx.x;
    const __nv_bfloat16* Lp = g_Lb + (size_t)b * 512 * 4096 + p;
    float m = 0.f, s = 0.f;    // logits >= 0 post-relu
#pragma unroll 8
    for (int c = 0; c < 512; c++) {
        float v = __bfloat162float(Lp[(size_t)c * 4096]);
        float mn = fmaxf(m, v);
        s = s * __expf(m - mn) + __expf(v - mn);
        m = mn;
    }
    float inv = 1.f / s;
    const float* xp = x + (size_t)b * 512 * 4096 + p;
    float* op = out + (size_t)b * 512 * 4096 + p;
#pragma unroll 8
    for (int c = 0; c < 512; c++) {
        float w = __expf(__bfloat162float(Lp[(size_t)c * 4096]) - m) * inv;
        float xv = xp[(size_t)c * 4096];
        op[(size_t)c * 4096] = fmaf(xv, w, xv);
    }
}

// ------------------------------- launcher -----------------------------------
extern "C" void kernel_launch(void* const* d_in, const int* in_sizes, int n_in,
                              void* d_out, int out_size) {
    (void)in_sizes; (void)n_in; (void)out_size;
    const float* x  = (const float*)d_in[0];
    const float* W1 = (const float*)d_in[1];
    const float* b1 = (const float*)d_in[2];
    const float* W2 = (const float*)d_in[3];
    const float* b2 = (const float*)d_in[4];
    const float* W3 = (const float*)d_in[5];
    const float* b3 = (const float*)d_in[6];
    float* out = (float*)d_out;

    __nv_bfloat16 *pW2b, *pW3b, *pAspb, *pAspTb, *pTb, *pYb, *pH1b, *pH2b, *pLb;
    unsigned *ph1, *ph2;
    cudaGetSymbolAddress((void**)&pAspb, g_Aspb);
    cudaGetSymbolAddress((void**)&pAspTb, g_AspTb);
    cudaGetSymbolAddress((void**)&pW2b, g_W2b);
    cudaGetSymbolAddress((void**)&pW3b, g_W3b);
    cudaGetSymbolAddress((void**)&pTb,  g_Tb);
    cudaGetSymbolAddress((void**)&pYb,  g_Yb);
    cudaGetSymbolAddress((void**)&pH1b, g_H1b);
    cudaGetSymbolAddress((void**)&pH2b, g_H2b);
    cudaGetSymbolAddress((void**)&pLb,  g_Lb);
    cudaGetSymbolAddress((void**)&ph1, g_hist1);
    cudaGetSymbolAddress((void**)&ph2, g_hist2);

    k_init_dct<<<1024, 256>>>();
    k_prep_b<<<2304, 256>>>(W2, W3);
    k_mkM<<<dim3(8, 8), 256>>>(W1);
    cudaMemsetAsync(ph1, 0, 2048 * sizeof(unsigned));
    cudaMemsetAsync(ph2, 0, 64 * sizeof(unsigned));

    // forward spatial DCT: x (fp32) -> Tb (bf16)
    k_sdct<<<1024, 256>>>(x, 0, pTb, pAspb, nullptr, 0);

    // forward channel DCT -> Dt bf16 (transposed) + coarse histogram
    k_fwdch<<<dim3(32, 4, 8), 256>>>();

    // bf16-domain exact rank-k thresholds
    k_selc<<<1, 4>>>();
    k_ref<<<2048, 256>>>();
    k_self<<<1, 4>>>();

    // fused masked channel-inverse + conv1 -> Yb (bf16)
    k_fmma<<<dim3(32, 1, 32), 256>>>();

    // inverse spatial DCT + bias + relu: Yb -> H1b
    k_sdct<<<1024, 256>>>(pYb, 1, pH1b, pAspTb, b1, 1);

    // conv2: 3x3 dil-2 + bias + relu
    k_cmma<<<dim3(32, 1, 32), 256>>>(pW2b, 9L*128*128, 128L*128, 128, 9,
                                     pH1b, 8L*128*4096, 128L*4096,
                                     pH2b, 8L*128*4096, 128L*4096,
                                     b2, 1, 4);

    // conv3: 1x1 -> logits Lb (bf16)
    k_cmma<<<dim3(32, 1, 32), 256>>>(pW3b, 128L*128, 0, 128, 1,
                                     pH2b, 8L*128*4096, 128L*4096,
                                     pLb, 128L*4096, 512L*4096,
                                     b3, 1, 4);

    // softmax (online) + residual gate
    k_softmax<<<dim3(32, 8), 128>>>(x, out);
}